// round 15
// baseline (speedup 1.0000x reference)
#include <cuda_runtime.h>
#include <cuda_bf16.h>
#include <math.h>
#include <stdint.h>

#define H_ 768
#define N_ 16
#define NLAYERS 6
#define NOUTS 38
#define BATCH 8
#define LMAX 2048
#define K2 1536          // stored fat-K width; logical K is 2304
#define NCH 36
#define NSTAGE 3
#define STAGE_BYTES 32768
#define GSMEM (NSTAGE * STAGE_BYTES)
#define CFSZ (8*N_*H_)
#define MROWS (BATCH*LMAX)
#define NT_GLU 12

__device__ float g_A [MROWS*H_];
__device__ float g_Bf[MROWS*H_];
__device__ float g_V [MROWS*2*H_];
__device__ float g_V2[MROWS*2*H_];
__device__ float g_S [(size_t)2*BATCH*32*2*N_*H_];   // NCv <= 32
__device__ float g_CF[NLAYERS*CFSZ];
__device__ __nv_bfloat16 g_A3 [(size_t)MROWS*K2];
__device__ __nv_bfloat16 g_W3 [(size_t)NLAYERS*2*H_*K2];
__device__ __nv_bfloat16 g_W3e[(size_t)H_*K2];

__device__ __forceinline__ int mapA(int c) { return (c < 24) ? c : c - 24; }
__device__ __forceinline__ int mapB(int c) { return (c < 12) ? c : c - 12; }

// ---------------------------------------------------------------------------
// helpers
// ---------------------------------------------------------------------------
__device__ __forceinline__ uint32_t smem_u32(const void* p) {
    uint32_t a;
    asm("{ .reg .u64 t; cvta.to.shared.u64 t, %1; cvt.u32.u64 %0, t; }"
        : "=r"(a) : "l"(p));
    return a;
}
__device__ __forceinline__ void ldm4(uint32_t* r, uint32_t addr) {
    asm volatile("ldmatrix.sync.aligned.m8n8.x4.shared.b16 {%0,%1,%2,%3}, [%4];"
                 : "=r"(r[0]), "=r"(r[1]), "=r"(r[2]), "=r"(r[3]) : "r"(addr));
}
__device__ __forceinline__ void mma16816(float* c, const uint32_t* a,
                                         const uint32_t* b) {
    asm volatile(
        "mma.sync.aligned.m16n8k16.row.col.f32.bf16.bf16.f32 "
        "{%0,%1,%2,%3}, {%4,%5,%6,%7}, {%8,%9}, {%0,%1,%2,%3};"
        : "+f"(c[0]), "+f"(c[1]), "+f"(c[2]), "+f"(c[3])
        : "r"(a[0]), "r"(a[1]), "r"(a[2]), "r"(a[3]), "r"(b[0]), "r"(b[1]));
}
__device__ __forceinline__ void cp16(uint32_t saddr, const void* g) {
    asm volatile("cp.async.cg.shared.global [%0], [%1], 16;"
                 :: "r"(saddr), "l"(g));
}
__device__ __forceinline__ void cp_commit() {
    asm volatile("cp.async.commit_group;" ::: "memory");
}
template <int Nw>
__device__ __forceinline__ void cp_wait() {
    asm volatile("cp.async.wait_group %0;" :: "n"(Nw) : "memory");
}
__device__ __forceinline__ void split_bf16(float x, __nv_bfloat16& hi,
                                           __nv_bfloat16& lo) {
    hi = __float2bfloat16(x);
    lo = __float2bfloat16(x - __bfloat162float(hi));
}
__device__ __forceinline__ __nv_bfloat162 pack2(__nv_bfloat16 a,
                                                __nv_bfloat16 b) {
    __nv_bfloat162 r; r.x = a; r.y = b; return r;
}

// ---------------------------------------------------------------------------
// HMMA bf16 GEMM over logical K=2304, deduped 2-segment storage.
// ---------------------------------------------------------------------------
__global__ void __launch_bounds__(256, 2)
hmma_gemm_kernel(const __nv_bfloat16* __restrict__ A3,
                 const __nv_bfloat16* __restrict__ B3,
                 const float* __restrict__ bias,
                 float* __restrict__ C, float* __restrict__ C2,
                 int Ncols, int nsplit) {
    extern __shared__ __align__(128) char smem[];
    const uint32_t sbase = smem_u32(smem);

    const int tid  = threadIdx.x;
    const int wid  = tid >> 5;
    const int lane = tid & 31;
    const int warp_m = wid >> 2;
    const int warp_n = wid & 3;
    const int m_base = warp_m * 64;
    const int n_base = warp_n * 32;

    const int kz    = (int)blockIdx.z;
    const int nch   = NCH / nsplit;
    const int kbase = kz * nch;
    float* Cout = (kz == 0) ? C : C2;
    const bool addb = (kz == 0);

    const int m0 = blockIdx.y * 128;
    const int n0 = blockIdx.x * 128;
    const __nv_bfloat16* Ab = A3 + (size_t)m0 * K2;
    const __nv_bfloat16* Bb = B3 + (size_t)n0 * K2;

    const int st_row = tid >> 3;
    const int st_seg = tid & 7;
    uint32_t st_off[4];
#pragma unroll
    for (int i = 0; i < 4; ++i) {
        int r = st_row + i * 32;
        st_off[i] = (uint32_t)(r * 128 + ((st_seg ^ (r & 7)) * 16));
    }

    int rA[4], xA[4];
#pragma unroll
    for (int mt = 0; mt < 4; ++mt) {
        rA[mt] = m_base + mt * 16 + (lane & 15);
        xA[mt] = rA[mt] & 7;
    }
    const int uhA = lane >> 4;
    int rB[2], xB[2];
#pragma unroll
    for (int nt2 = 0; nt2 < 2; ++nt2) {
        rB[nt2] = n_base + nt2 * 16 + ((lane >> 4) << 3) + (lane & 7);
        xB[nt2] = rB[nt2] & 7;
    }
    const int uhB = (lane >> 3) & 1;

    float acc[4][4][4];
#pragma unroll
    for (int mt = 0; mt < 4; ++mt)
#pragma unroll
        for (int nt = 0; nt < 4; ++nt)
#pragma unroll
            for (int e = 0; e < 4; ++e) acc[mt][nt][e] = 0.0f;

#pragma unroll
    for (int s = 0; s < NSTAGE - 1; ++s) {
        uint32_t sa = sbase + s * STAGE_BYTES;
        uint32_t sb = sa + 16384;
        int lcA = mapA(kbase + s), lcB = mapB(kbase + s);
#pragma unroll
        for (int i = 0; i < 4; ++i) {
            int r = st_row + i * 32;
            cp16(sa + st_off[i], Ab + (size_t)r * K2 + lcA * 64 + st_seg * 8);
            cp16(sb + st_off[i], Bb + (size_t)r * K2 + lcB * 64 + st_seg * 8);
        }
        cp_commit();
    }

    uint32_t cur_s = sbase;
    uint32_t pf_s  = sbase + (NSTAGE - 1) * STAGE_BYTES;
    for (int c = 0; c < nch; ++c) {
        cp_wait<NSTAGE - 2>();
        __syncthreads();
        int pf = c + NSTAGE - 1;
        if (pf < nch) {
            uint32_t sa = pf_s;
            uint32_t sb = sa + 16384;
            int lcA = mapA(kbase + pf), lcB = mapB(kbase + pf);
#pragma unroll
            for (int i = 0; i < 4; ++i) {
                int r = st_row + i * 32;
                cp16(sa + st_off[i], Ab + (size_t)r * K2 + lcA * 64 + st_seg * 8);
                cp16(sb + st_off[i], Bb + (size_t)r * K2 + lcB * 64 + st_seg * 8);
            }
        }
        cp_commit();

        uint32_t sa = cur_s;
        uint32_t sb = sa + 16384;
#pragma unroll
        for (int kk = 0; kk < 4; ++kk) {
            uint32_t af[4][4], bf[2][4];
#pragma unroll
            for (int mt = 0; mt < 4; ++mt)
                ldm4(af[mt], sa + (uint32_t)(rA[mt] * 128 +
                             (((kk * 2 + uhA) ^ xA[mt]) * 16)));
#pragma unroll
            for (int nt2 = 0; nt2 < 2; ++nt2)
                ldm4(bf[nt2], sb + (uint32_t)(rB[nt2] * 128 +
                              (((kk * 2 + uhB) ^ xB[nt2]) * 16)));
#pragma unroll
            for (int mt = 0; mt < 4; ++mt)
#pragma unroll
                for (int nt = 0; nt < 4; ++nt)
                    mma16816(acc[mt][nt], af[mt], &bf[nt >> 1][(nt & 1) * 2]);
        }
        cur_s += STAGE_BYTES;
        if (cur_s == sbase + NSTAGE * STAGE_BYTES) cur_s = sbase;
        pf_s += STAGE_BYTES;
        if (pf_s == sbase + NSTAGE * STAGE_BYTES) pf_s = sbase;
    }

    const int gr = lane >> 2;
    const int gc = (lane & 3) * 2;
#pragma unroll
    for (int nt = 0; nt < 4; ++nt) {
        int ncol = n0 + n_base + nt * 8 + gc;
        float b0 = addb ? bias[ncol] : 0.0f;
        float b1 = addb ? bias[ncol + 1] : 0.0f;
#pragma unroll
        for (int mt = 0; mt < 4; ++mt) {
            int mr = m0 + m_base + mt * 16 + gr;
            float2 v0 = make_float2(acc[mt][nt][0] + b0, acc[mt][nt][1] + b1);
            float2 v1 = make_float2(acc[mt][nt][2] + b0, acc[mt][nt][3] + b1);
            *(float2*)&Cout[(size_t)mr * Ncols + ncol] = v0;
            *(float2*)&Cout[(size_t)(mr + 8) * Ncols + ncol] = v1;
        }
    }
}

// ---------------------------------------------------------------------------
// Unified prep kernel (wconv_layers | wconv_enc | coef | enc1)
// ---------------------------------------------------------------------------
#define PREP_WL ((NLAYERS * 2 * H_ * (H_ / 2)) / 256)
#define PREP_WE ((H_ / 32) * (H_ / 32))
#define PREP_CO ((H_ * N_ * NLAYERS) / 256)

__global__ void prep_kernel(const float* __restrict__ out_w,
                            const float* __restrict__ w2,
                            const float* __restrict__ log_dt,
                            const float* __restrict__ log_A_real,
                            const float* __restrict__ A_imag,
                            const float* __restrict__ C_ri,
                            const float* __restrict__ xr,
                            const float* __restrict__ w1,
                            const float* __restrict__ b1) {
    int blk = blockIdx.x;
    int tid = threadIdx.x;

    if (blk < PREP_WL) {
        size_t idx = (size_t)blk * 256 + tid;
        int kp = idx % (H_ / 2);
        size_t nr = idx / (H_ / 2);
        int j = kp * 2;
        float2 w = *(const float2*)&out_w[nr * H_ + j];
        __nv_bfloat16 h0, l0, h1, l1;
        split_bf16(w.x, h0, l0);
        split_bf16(w.y, h1, l1);
        __nv_bfloat16* dst = g_W3 + nr * K2;
        *(__nv_bfloat162*)&dst[j]      = pack2(h0, h1);
        *(__nv_bfloat162*)&dst[H_ + j] = pack2(l0, l1);
        return;
    }
    blk -= PREP_WL;
    if (blk < PREP_WE) {
        __shared__ float t[32][33];
        int bx = blk % (H_ / 32), by = blk / (H_ / 32);
        int k0 = by * 32, n0 = bx * 32;
        int tx = tid & 31, ty = tid >> 5;
#pragma unroll
        for (int i = ty; i < 32; i += 8)
            t[i][tx] = w2[(size_t)(k0 + i) * H_ + n0 + tx];
        __syncthreads();
#pragma unroll
        for (int i = ty; i < 32; i += 8) {
            float w = t[tx][i];
            __nv_bfloat16 hi, lo; split_bf16(w, hi, lo);
            __nv_bfloat16* dst = g_W3e + (size_t)(n0 + i) * K2;
            dst[k0 + tx] = hi; dst[H_ + k0 + tx] = lo;
        }
        return;
    }
    blk -= PREP_WE;
    if (blk < PREP_CO) {
        int gidx = blk * 256 + tid;
        int layer = gidx / (H_ * N_);
        int idx   = gidx % (H_ * N_);
        int h = idx % H_;
        int n = idx / H_;
        int CLl = (layer <= 1) ? 64 : 32;

        float dt  = expf(log_dt[layer * H_ + h]);
        int pidx  = (layer * H_ + h) * N_ + n;
        float Are = -expf(log_A_real[pidx]);
        float Aim = A_imag[pidx];
        float dr = dt * Are, di = dt * Aim;
        float e  = expf(dr);
        float ar = e * cosf(di);
        float ai = e * sinf(di);
        float invA2 = 1.0f / (Are * Are + Aim * Aim);
        float dBr = ((ar - 1.0f) * Are + ai * Aim) * invA2;
        float dBi = (ai * Are - (ar - 1.0f) * Aim) * invA2;

        size_t c0idx = ((((size_t)layer * 2 + 0) * H_ + h) * N_ + n) * 2;
        size_t c1idx = ((((size_t)layer * 2 + 1) * H_ + h) * N_ + n) * 2;
        float c0r = C_ri[c0idx], c0i = C_ri[c0idx + 1];
        float c1r = C_ri[c1idx], c1i = C_ri[c1idx + 1];

        float eL = expf(CLl * dr);
        float* cf = g_CF + layer * CFSZ;
        cf[(0 * N_ + n) * H_ + h] = ar;
        cf[(1 * N_ + n) * H_ + h] = ai;
        cf[(2 * N_ + n) * H_ + h] = c0r * dBr - c0i * dBi;
        cf[(3 * N_ + n) * H_ + h] = c0r * dBi + c0i * dBr;
        cf[(4 * N_ + n) * H_ + h] = c1r * dBr - c1i * dBi;
        cf[(5 * N_ + n) * H_ + h] = c1r * dBi + c1i * dBr;
        cf[(6 * N_ + n) * H_ + h] = eL * cosf(CLl * di);
        cf[(7 * N_ + n) * H_ + h] = eL * sinf(CLl * di);
        return;
    }
    blk -= PREP_CO;
    {
        int row = blk;
        __shared__ float xs[8];
        if (tid < 8) xs[tid] = xr[(size_t)row * 8 + tid];
        __syncthreads();
        if (tid >= 192) return;
        __nv_bfloat16* dst = g_A3 + (size_t)row * K2;
#pragma unroll
        for (int p = tid; p < H_ / 2; p += 192) {
            int j = p * 2;
            float2 bv = *(const float2*)&b1[j];
            float s0 = bv.x, s1 = bv.y;
#pragma unroll
            for (int k = 0; k < 8; ++k) {
                float2 wv = *(const float2*)&w1[k * H_ + j];
                s0 = fmaf(xs[k], wv.x, s0);
                s1 = fmaf(xs[k], wv.y, s1);
            }
            float v0 = s0 / (1.0f + fabsf(s0));
            float v1 = s1 / (1.0f + fabsf(s1));
            __nv_bfloat16 h0, l0, h1, l1;
            split_bf16(v0, h0, l0);
            split_bf16(v1, h1, l1);
            *(__nv_bfloat162*)&dst[j]      = pack2(h0, h1);
            *(__nv_bfloat162*)&dst[H_ + j] = pack2(l0, l1);
        }
    }
}

// ---------------------------------------------------------------------------
// Scan pass 1: both directions, X read directly. Runtime CL.
// ---------------------------------------------------------------------------
__global__ void scan_pass1(const float* __restrict__ X, int L, int CL,
                           int layer) {
    int h   = blockIdx.x * 256 + threadIdx.x;
    int c   = blockIdx.y;
    int NCv = gridDim.y;
    int b   = blockIdx.z;
    int lo  = c * CL;
    const float* cf = g_CF + layer * CFSZ;

    float ar[N_], ai[N_], sr[N_], si[N_];
#pragma unroll
    for (int n = 0; n < N_; ++n) {
        ar[n] = cf[(0 * N_ + n) * H_ + h];
        ai[n] = cf[(1 * N_ + n) * H_ + h];
        sr[n] = 0.0f; si[n] = 0.0f;
    }
    const float* xp = X + ((size_t)b * L + lo) * H_ + h;
#pragma unroll 2
    for (int k = 0; k < CL; ++k) {
        float u = xp[(size_t)k * H_];
#pragma unroll
        for (int n = 0; n < N_; ++n) {
            float t = fmaf(ar[n], sr[n], fmaf(-ai[n], si[n], u));
            si[n] = fmaf(ar[n], si[n], ai[n] * sr[n]);
            sr[n] = t;
        }
    }
    float* f0 = g_S + (((size_t)(0 * BATCH + b) * NCv + c) * 32) * H_ + h;
#pragma unroll
    for (int n = 0; n < N_; ++n) {
        f0[(2 * n + 0) * H_] = sr[n];
        f0[(2 * n + 1) * H_] = si[n];
        sr[n] = 0.0f; si[n] = 0.0f;
    }
#pragma unroll 2
    for (int k = CL - 1; k >= 0; --k) {
        float u = xp[(size_t)k * H_];
#pragma unroll
        for (int n = 0; n < N_; ++n) {
            float t = fmaf(ar[n], sr[n], fmaf(-ai[n], si[n], u));
            si[n] = fmaf(ar[n], si[n], ai[n] * sr[n]);
            sr[n] = t;
        }
    }
    float* f1 = g_S + (((size_t)(1 * BATCH + b) * NCv + c) * 32) * H_ + h;
#pragma unroll
    for (int n = 0; n < N_; ++n) {
        f1[(2 * n + 0) * H_] = sr[n];
        f1[(2 * n + 1) * H_] = si[n];
    }
}

// ---------------------------------------------------------------------------
// Scan fix: tiled (8) batched loads, serial compose + stores.
// ---------------------------------------------------------------------------
__global__ void scan_fix(int NCv, int layer) {
    int idx = blockIdx.x * blockDim.x + threadIdx.x;
    int h   = idx % H_;
    int n   = (idx / H_) % N_;
    int b   = (idx / (H_ * N_)) % BATCH;
    int dir = idx / (H_ * N_ * BATCH);
    const float* cf = g_CF + layer * CFSZ;

    float aLr = cf[(6 * N_ + n) * H_ + h];
    float aLi = cf[(7 * N_ + n) * H_ + h];

    float* base = g_S + ((size_t)(dir * BATCH + b) * NCv * 32) * H_
                + (2 * n) * H_ + h;
    float accr = 0.0f, acci = 0.0f;
    for (int c0 = 0; c0 < NCv; c0 += 8) {
        float fr[8], fi[8];
#pragma unroll
        for (int i = 0; i < 8; ++i) {
            int cc = (dir == 0) ? (c0 + i) : (NCv - 1 - (c0 + i));
            float* p = base + (size_t)cc * 32 * H_;
            fr[i] = p[0];
            fi[i] = p[H_];
        }
#pragma unroll
        for (int i = 0; i < 8; ++i) {
            int cc = (dir == 0) ? (c0 + i) : (NCv - 1 - (c0 + i));
            float* p = base + (size_t)cc * 32 * H_;
            p[0]  = accr;
            p[H_] = acci;
            float t = aLr * accr - aLi * acci + fr[i];
            acci = aLr * acci + aLi * accr + fi[i];
            accr = t;
        }
    }
}

// ---------------------------------------------------------------------------
// Scan pass 2 (merged bwd+fwd). ybuf = dynamic smem (CL*1KB). Runtime CL.
// ---------------------------------------------------------------------------
__global__ void scan_pass2(const float* __restrict__ X,
                           const float* __restrict__ Dv,
                           int L, int CL, int Lout, int ds, int layer) {
    extern __shared__ float ybuf[];
    int h   = blockIdx.x * 256 + threadIdx.x;
    int c   = blockIdx.y;
    int NCv = gridDim.y;
    int b   = blockIdx.z;
    int tid = threadIdx.x;
    int lo  = c * CL;
    const float* cf = g_CF + layer * CFSZ;

    float ar[N_], ai[N_];
#pragma unroll
    for (int n = 0; n < N_; ++n) {
        ar[n] = cf[(0 * N_ + n) * H_ + h];
        ai[n] = cf[(1 * N_ + n) * H_ + h];
    }
    const float* xp = X + ((size_t)b * L + lo) * H_ + h;

    {
        float wr[N_], wi[N_], sr[N_], si[N_];
        const float* stp =
            g_S + (((size_t)(1 * BATCH + b) * NCv + c) * 32) * H_ + h;
#pragma unroll
        for (int n = 0; n < N_; ++n) {
            wr[n] = cf[(4 * N_ + n) * H_ + h];
            wi[n] = cf[(5 * N_ + n) * H_ + h];
            sr[n] = stp[(2 * n + 0) * H_];
            si[n] = stp[(2 * n + 1) * H_];
        }
#pragma unroll 2
        for (int k = CL - 1; k >= 0; --k) {
            int p = lo + k;
            if (!ds || !(p & 1)) {
                float a0 = 0.0f, a1 = 0.0f;
#pragma unroll
                for (int n = 0; n < N_; ++n) {
                    a0 = fmaf(wr[n], sr[n], a0);
                    a1 = fmaf(wi[n], si[n], a1);
                }
                ybuf[k * 256 + tid] = 2.0f * (a0 - a1);
            }
            float u = xp[(size_t)k * H_];
#pragma unroll
            for (int n = 0; n < N_; ++n) {
                float t = fmaf(ar[n], sr[n], fmaf(-ai[n], si[n], u));
                si[n] = fmaf(ar[n], si[n], ai[n] * sr[n]);
                sr[n] = t;
            }
        }
    }

    {
        float wr[N_], wi[N_], sr[N_], si[N_];
        const float* stp =
            g_S + (((size_t)(0 * BATCH + b) * NCv + c) * 32) * H_ + h;
#pragma unroll
        for (int n = 0; n < N_; ++n) {
            wr[n] = cf[(2 * N_ + n) * H_ + h];
            wi[n] = cf[(3 * N_ + n) * H_ + h];
            sr[n] = stp[(2 * n + 0) * H_];
            si[n] = stp[(2 * n + 1) * H_];
        }
        float Dh = Dv[h];
#pragma unroll 2
        for (int k = 0; k < CL; ++k) {
            float u = xp[(size_t)k * H_];
#pragma unroll
            for (int n = 0; n < N_; ++n) {
                float t = fmaf(ar[n], sr[n], fmaf(-ai[n], si[n], u));
                si[n] = fmaf(ar[n], si[n], ai[n] * sr[n]);
                sr[n] = t;
            }
            int l = lo + k;
            if (!ds || !(l & 1)) {
                float a0 = 0.0f, a1 = 0.0f;
#pragma unroll
                for (int n = 0; n < N_; ++n) {
                    a0 = fmaf(wr[n], sr[n], a0);
                    a1 = fmaf(wi[n], si[n], a1);
                }
                int lrow = ds ? (l >> 1) : l;
                size_t rr = (size_t)b * Lout + lrow;
                float yv = 2.0f * (a0 - a1) + ybuf[k * 256 + tid] + Dh * u;
                yv = 0.5f * yv * (1.0f + erff(yv * 0.70710678118654752f));
                __nv_bfloat16 hi, lo2; split_bf16(yv, hi, lo2);
                __nv_bfloat16* dst = g_A3 + rr * K2;
                dst[h] = hi; dst[H_ + h] = lo2;
            }
        }
    }
}

// ---------------------------------------------------------------------------
// GLU + residual + LayerNorm. WARP-PER-ROW: 8 rows/block, 256 threads,
// warp-local butterfly reduction, no block barriers.
// ---------------------------------------------------------------------------
__global__ void __launch_bounds__(256)
glu_ln_kernel(const float* __restrict__ V,
              const float* __restrict__ V2,
              const float* __restrict__ X,
              const float* __restrict__ nw,
              const float* __restrict__ nb,
              float* __restrict__ out, int ds) {
    int warp = threadIdx.x >> 5;
    int lane = threadIdx.x & 31;
    int row_out = blockIdx.x * 8 + warp;
    int row_in  = ds ? row_out * 2 : row_out;
    const float4* v4  = (const float4*)(V  + (size_t)row_out * (2 * H_));
    const float4* v24 = (const float4*)(V2 + (size_t)row_out * (2 * H_));
    const float4* x4  = (const float4*)(X + (size_t)row_in * H_);

    float4 z[6];
    float s = 0.0f, q = 0.0f;
#pragma unroll
    for (int j = 0; j < 6; ++j) {
        int idx = lane + 32 * j;
        float4 a  = v4[idx];
        float4 g  = v4[192 + idx];
        float4 a2 = v24[idx];
        float4 g2 = v24[192 + idx];
        a.x += a2.x; a.y += a2.y; a.z += a2.z; a.w += a2.w;
        g.x += g2.x; g.y += g2.y; g.z += g2.z; g.w += g2.w;
        float4 x = x4[idx];
        float4 zz;
        zz.x = a.x / (1.0f + expf(-g.x)) + x.x;
        zz.y = a.y / (1.0f + expf(-g.y)) + x.y;
        zz.z = a.z / (1.0f + expf(-g.z)) + x.z;
        zz.w = a.w / (1.0f + expf(-g.w)) + x.w;
        z[j] = zz;
        s += zz.x + zz.y + zz.z + zz.w;
        q += zz.x * zz.x + zz.y * zz.y + zz.z * zz.z + zz.w * zz.w;
    }
#pragma unroll
    for (int o = 16; o; o >>= 1) {
        s += __shfl_xor_sync(0xffffffffu, s, o);
        q += __shfl_xor_sync(0xffffffffu, q, o);
    }
    float mu  = s * (1.0f / H_);
    float inv = rsqrtf(q * (1.0f / H_) - mu * mu + 1e-5f);

    float4* o4 = (float4*)(out + (size_t)row_out * H_);
#pragma unroll
    for (int j = 0; j < 6; ++j) {
        int idx = lane + 32 * j;
        float4 w = ((const float4*)nw)[idx];
        float4 bb = ((const float4*)nb)[idx];
        float4 zz = z[j];
        float4 o;
        o.x = (zz.x - mu) * inv * w.x + bb.x;
        o.y = (zz.y - mu) * inv * w.y + bb.y;
        o.z = (zz.z - mu) * inv * w.z + bb.z;
        o.w = (zz.w - mu) * inv * w.w + bb.w;
        o4[idx] = o;
    }
}

// ---------------------------------------------------------------------------
// Head
// ---------------------------------------------------------------------------
__global__ void head_kernel(const float* __restrict__ X,
                            const float* __restrict__ W,
                            const float* __restrict__ bb,
                            float* __restrict__ out) {
    int row = blockIdx.x;
    __shared__ float xs[H_];
    for (int j = threadIdx.x; j < H_; j += blockDim.x)
        xs[j] = X[(size_t)row * H_ + j];
    __syncthreads();
    int d = threadIdx.x;
    if (d < NOUTS) {
        float sum = bb[d];
#pragma unroll 4
        for (int k = 0; k < H_; ++k)
            sum = fmaf(xs[k], W[k * NOUTS + d], sum);
        out[(size_t)row * NOUTS + d] = sum;
    }
}

// ---------------------------------------------------------------------------
extern "C" void kernel_launch(void* const* d_in, const int* in_sizes, int n_in,
                              void* d_out, int out_size) {
    const float* x_raw      = (const float*)d_in[1];
    const float* enc_w1     = (const float*)d_in[3];
    const float* enc_b1     = (const float*)d_in[4];
    const float* enc_w2     = (const float*)d_in[5];
    const float* enc_b2     = (const float*)d_in[6];
    const float* log_dt     = (const float*)d_in[7];
    const float* log_A_real = (const float*)d_in[8];
    const float* A_imag     = (const float*)d_in[9];
    const float* C_ri       = (const float*)d_in[10];
    const float* Dv         = (const float*)d_in[11];
    const float* out_w      = (const float*)d_in[12];
    const float* out_b      = (const float*)d_in[13];
    const float* norm_w     = (const float*)d_in[14];
    const float* norm_b     = (const float*)d_in[15];
    const float* wout_w     = (const float*)d_in[16];
    const float* wout_b     = (const float*)d_in[17];

    float *gA, *gB, *gV, *gV2;
    cudaGetSymbolAddress((void**)&gA,  g_A);
    cudaGetSymbolAddress((void**)&gB,  g_Bf);
    cudaGetSymbolAddress((void**)&gV,  g_V);
    cudaGetSymbolAddress((void**)&gV2, g_V2);
    __nv_bfloat16 *gA3, *gW3, *gW3e;
    cudaGetSymbolAddress((void**)&gA3,  g_A3);
    cudaGetSymbolAddress((void**)&gW3,  g_W3);
    cudaGetSymbolAddress((void**)&gW3e, g_W3e);

    cudaFuncSetAttribute(hmma_gemm_kernel,
                         cudaFuncAttributeMaxDynamicSharedMemorySize, GSMEM);
    cudaFuncSetAttribute(scan_pass2,
                         cudaFuncAttributeMaxDynamicSharedMemorySize, 65536);

    prep_kernel<<<PREP_WL + PREP_WE + PREP_CO + MROWS, 256>>>(
        out_w, enc_w2, log_dt, log_A_real, A_imag, C_ri,
        x_raw, enc_w1, enc_b1);

    hmma_gemm_kernel<<<dim3(H_ / 128, MROWS / 128, 1), 256, GSMEM>>>(
        gA3, gW3e, enc_b2, gA, gV2, H_, 1);

    int Lcur = LMAX;
    float* cur = gA;
    float* nxt = gB;
    for (int i = 0; i < NLAYERS; ++i) {
        int ds   = (i <= 2) ? 1 : 0;
        int Lout = ds ? Lcur / 2 : Lcur;
        int CL   = (i <= 1) ? 64 : 32;
        int NCv  = Lcur / CL;
        int Mout = BATCH * Lout;
        int ysm  = CL * 256 * 4;

        scan_pass1<<<dim3(3, NCv, BATCH), 256>>>(cur, Lcur, CL, i);
        scan_fix<<<(2 * BATCH * H_ * N_) / 256, 256>>>(NCv, i);
        scan_pass2<<<dim3(3, NCv, BATCH), 256, ysm>>>(cur, Dv + i * H_,
                                                      Lcur, CL, Lout, ds, i);
        dim3 ggrid(NT_GLU, Mout / 128, 2);
        hmma_gemm_kernel<<<ggrid, 256, GSMEM>>>(
            gA3, gW3 + (size_t)i * 2 * H_ * K2, out_b + (size_t)i * 2 * H_,
            gV, gV2, 2 * H_, 2);
        glu_ln_kernel<<<Mout / 8, 256>>>(gV, gV2, cur, norm_w + i * H_,
                                         norm_b + i * H_, nxt, ds);
        Lcur = Lout;
        float* tmp = cur; cur = nxt; nxt = tmp;
    }

    head_kernel<<<BATCH * Lcur, 128>>>(cur, wout_w, wout_b, (float*)d_out);
}

// round 16
// speedup vs baseline: 1.4933x; 1.4933x over previous
#include <cuda_runtime.h>
#include <cuda_bf16.h>
#include <math.h>
#include <stdint.h>

#define H_ 768
#define N_ 16
#define NLAYERS 6
#define NOUTS 38
#define BATCH 8
#define LMAX 2048
#define K2 1536          // stored fat-K width; logical K is 2304
#define NCH 36
#define NSTAGE 3
#define STAGE_BYTES 32768
#define GSMEM (NSTAGE * STAGE_BYTES)
#define CFSZ (8*N_*H_)
#define MROWS (BATCH*LMAX)
#define NT_GLU 12

__device__ float g_A [MROWS*H_];
__device__ float g_Bf[MROWS*H_];
__device__ float g_V [MROWS*2*H_];
__device__ float g_V2[MROWS*2*H_];
__device__ float g_S [(size_t)2*BATCH*32*2*N_*H_];   // NCv <= 32
__device__ float g_CF[NLAYERS*CFSZ];
__device__ __nv_bfloat16 g_A3 [(size_t)MROWS*K2];
__device__ __nv_bfloat16 g_W3 [(size_t)NLAYERS*2*H_*K2];
__device__ __nv_bfloat16 g_W3e[(size_t)H_*K2];

__device__ __forceinline__ int mapA(int c) { return (c < 24) ? c : c - 24; }
__device__ __forceinline__ int mapB(int c) { return (c < 12) ? c : c - 12; }

// ---------------------------------------------------------------------------
// helpers
// ---------------------------------------------------------------------------
__device__ __forceinline__ uint32_t smem_u32(const void* p) {
    uint32_t a;
    asm("{ .reg .u64 t; cvta.to.shared.u64 t, %1; cvt.u32.u64 %0, t; }"
        : "=r"(a) : "l"(p));
    return a;
}
__device__ __forceinline__ void ldm4(uint32_t* r, uint32_t addr) {
    asm volatile("ldmatrix.sync.aligned.m8n8.x4.shared.b16 {%0,%1,%2,%3}, [%4];"
                 : "=r"(r[0]), "=r"(r[1]), "=r"(r[2]), "=r"(r[3]) : "r"(addr));
}
__device__ __forceinline__ void mma16816(float* c, const uint32_t* a,
                                         const uint32_t* b) {
    asm volatile(
        "mma.sync.aligned.m16n8k16.row.col.f32.bf16.bf16.f32 "
        "{%0,%1,%2,%3}, {%4,%5,%6,%7}, {%8,%9}, {%0,%1,%2,%3};"
        : "+f"(c[0]), "+f"(c[1]), "+f"(c[2]), "+f"(c[3])
        : "r"(a[0]), "r"(a[1]), "r"(a[2]), "r"(a[3]), "r"(b[0]), "r"(b[1]));
}
__device__ __forceinline__ void cp16(uint32_t saddr, const void* g) {
    asm volatile("cp.async.cg.shared.global [%0], [%1], 16;"
                 :: "r"(saddr), "l"(g));
}
__device__ __forceinline__ void cp_commit() {
    asm volatile("cp.async.commit_group;" ::: "memory");
}
template <int Nw>
__device__ __forceinline__ void cp_wait() {
    asm volatile("cp.async.wait_group %0;" :: "n"(Nw) : "memory");
}
__device__ __forceinline__ void split_bf16(float x, __nv_bfloat16& hi,
                                           __nv_bfloat16& lo) {
    hi = __float2bfloat16(x);
    lo = __float2bfloat16(x - __bfloat162float(hi));
}
__device__ __forceinline__ __nv_bfloat162 pack2(__nv_bfloat16 a,
                                                __nv_bfloat16 b) {
    __nv_bfloat162 r; r.x = a; r.y = b; return r;
}

// ---------------------------------------------------------------------------
// HMMA bf16 GEMM over logical K=2304, deduped 2-segment storage.
// ---------------------------------------------------------------------------
__global__ void __launch_bounds__(256, 2)
hmma_gemm_kernel(const __nv_bfloat16* __restrict__ A3,
                 const __nv_bfloat16* __restrict__ B3,
                 const float* __restrict__ bias,
                 float* __restrict__ C, float* __restrict__ C2,
                 int Ncols, int nsplit) {
    extern __shared__ __align__(128) char smem[];
    const uint32_t sbase = smem_u32(smem);

    const int tid  = threadIdx.x;
    const int wid  = tid >> 5;
    const int lane = tid & 31;
    const int warp_m = wid >> 2;
    const int warp_n = wid & 3;
    const int m_base = warp_m * 64;
    const int n_base = warp_n * 32;

    const int kz    = (int)blockIdx.z;
    const int nch   = NCH / nsplit;
    const int kbase = kz * nch;
    float* Cout = (kz == 0) ? C : C2;
    const bool addb = (kz == 0);

    const int m0 = blockIdx.y * 128;
    const int n0 = blockIdx.x * 128;
    const __nv_bfloat16* Ab = A3 + (size_t)m0 * K2;
    const __nv_bfloat16* Bb = B3 + (size_t)n0 * K2;

    const int st_row = tid >> 3;
    const int st_seg = tid & 7;
    uint32_t st_off[4];
#pragma unroll
    for (int i = 0; i < 4; ++i) {
        int r = st_row + i * 32;
        st_off[i] = (uint32_t)(r * 128 + ((st_seg ^ (r & 7)) * 16));
    }

    int rA[4], xA[4];
#pragma unroll
    for (int mt = 0; mt < 4; ++mt) {
        rA[mt] = m_base + mt * 16 + (lane & 15);
        xA[mt] = rA[mt] & 7;
    }
    const int uhA = lane >> 4;
    int rB[2], xB[2];
#pragma unroll
    for (int nt2 = 0; nt2 < 2; ++nt2) {
        rB[nt2] = n_base + nt2 * 16 + ((lane >> 4) << 3) + (lane & 7);
        xB[nt2] = rB[nt2] & 7;
    }
    const int uhB = (lane >> 3) & 1;

    float acc[4][4][4];
#pragma unroll
    for (int mt = 0; mt < 4; ++mt)
#pragma unroll
        for (int nt = 0; nt < 4; ++nt)
#pragma unroll
            for (int e = 0; e < 4; ++e) acc[mt][nt][e] = 0.0f;

#pragma unroll
    for (int s = 0; s < NSTAGE - 1; ++s) {
        uint32_t sa = sbase + s * STAGE_BYTES;
        uint32_t sb = sa + 16384;
        int lcA = mapA(kbase + s), lcB = mapB(kbase + s);
#pragma unroll
        for (int i = 0; i < 4; ++i) {
            int r = st_row + i * 32;
            cp16(sa + st_off[i], Ab + (size_t)r * K2 + lcA * 64 + st_seg * 8);
            cp16(sb + st_off[i], Bb + (size_t)r * K2 + lcB * 64 + st_seg * 8);
        }
        cp_commit();
    }

    uint32_t cur_s = sbase;
    uint32_t pf_s  = sbase + (NSTAGE - 1) * STAGE_BYTES;
    for (int c = 0; c < nch; ++c) {
        cp_wait<NSTAGE - 2>();
        __syncthreads();
        int pf = c + NSTAGE - 1;
        if (pf < nch) {
            uint32_t sa = pf_s;
            uint32_t sb = sa + 16384;
            int lcA = mapA(kbase + pf), lcB = mapB(kbase + pf);
#pragma unroll
            for (int i = 0; i < 4; ++i) {
                int r = st_row + i * 32;
                cp16(sa + st_off[i], Ab + (size_t)r * K2 + lcA * 64 + st_seg * 8);
                cp16(sb + st_off[i], Bb + (size_t)r * K2 + lcB * 64 + st_seg * 8);
            }
        }
        cp_commit();

        uint32_t sa = cur_s;
        uint32_t sb = sa + 16384;
#pragma unroll
        for (int kk = 0; kk < 4; ++kk) {
            uint32_t af[4][4], bf[2][4];
#pragma unroll
            for (int mt = 0; mt < 4; ++mt)
                ldm4(af[mt], sa + (uint32_t)(rA[mt] * 128 +
                             (((kk * 2 + uhA) ^ xA[mt]) * 16)));
#pragma unroll
            for (int nt2 = 0; nt2 < 2; ++nt2)
                ldm4(bf[nt2], sb + (uint32_t)(rB[nt2] * 128 +
                              (((kk * 2 + uhB) ^ xB[nt2]) * 16)));
#pragma unroll
            for (int mt = 0; mt < 4; ++mt)
#pragma unroll
                for (int nt = 0; nt < 4; ++nt)
                    mma16816(acc[mt][nt], af[mt], &bf[nt >> 1][(nt & 1) * 2]);
        }
        cur_s += STAGE_BYTES;
        if (cur_s == sbase + NSTAGE * STAGE_BYTES) cur_s = sbase;
        pf_s += STAGE_BYTES;
        if (pf_s == sbase + NSTAGE * STAGE_BYTES) pf_s = sbase;
    }

    const int gr = lane >> 2;
    const int gc = (lane & 3) * 2;
#pragma unroll
    for (int nt = 0; nt < 4; ++nt) {
        int ncol = n0 + n_base + nt * 8 + gc;
        float b0 = addb ? bias[ncol] : 0.0f;
        float b1 = addb ? bias[ncol + 1] : 0.0f;
#pragma unroll
        for (int mt = 0; mt < 4; ++mt) {
            int mr = m0 + m_base + mt * 16 + gr;
            float2 v0 = make_float2(acc[mt][nt][0] + b0, acc[mt][nt][1] + b1);
            float2 v1 = make_float2(acc[mt][nt][2] + b0, acc[mt][nt][3] + b1);
            *(float2*)&Cout[(size_t)mr * Ncols + ncol] = v0;
            *(float2*)&Cout[(size_t)(mr + 8) * Ncols + ncol] = v1;
        }
    }
}

// ---------------------------------------------------------------------------
// Unified prep kernel (wconv_layers | wconv_enc | coef | enc1)
// ---------------------------------------------------------------------------
#define PREP_WL ((NLAYERS * 2 * H_ * (H_ / 2)) / 256)
#define PREP_WE ((H_ / 32) * (H_ / 32))
#define PREP_CO ((H_ * N_ * NLAYERS) / 256)

__global__ void prep_kernel(const float* __restrict__ out_w,
                            const float* __restrict__ w2,
                            const float* __restrict__ log_dt,
                            const float* __restrict__ log_A_real,
                            const float* __restrict__ A_imag,
                            const float* __restrict__ C_ri,
                            const float* __restrict__ xr,
                            const float* __restrict__ w1,
                            const float* __restrict__ b1) {
    int blk = blockIdx.x;
    int tid = threadIdx.x;

    if (blk < PREP_WL) {
        size_t idx = (size_t)blk * 256 + tid;
        int kp = idx % (H_ / 2);
        size_t nr = idx / (H_ / 2);
        int j = kp * 2;
        float2 w = *(const float2*)&out_w[nr * H_ + j];
        __nv_bfloat16 h0, l0, h1, l1;
        split_bf16(w.x, h0, l0);
        split_bf16(w.y, h1, l1);
        __nv_bfloat16* dst = g_W3 + nr * K2;
        *(__nv_bfloat162*)&dst[j]      = pack2(h0, h1);
        *(__nv_bfloat162*)&dst[H_ + j] = pack2(l0, l1);
        return;
    }
    blk -= PREP_WL;
    if (blk < PREP_WE) {
        __shared__ float t[32][33];
        int bx = blk % (H_ / 32), by = blk / (H_ / 32);
        int k0 = by * 32, n0 = bx * 32;
        int tx = tid & 31, ty = tid >> 5;
#pragma unroll
        for (int i = ty; i < 32; i += 8)
            t[i][tx] = w2[(size_t)(k0 + i) * H_ + n0 + tx];
        __syncthreads();
#pragma unroll
        for (int i = ty; i < 32; i += 8) {
            float w = t[tx][i];
            __nv_bfloat16 hi, lo; split_bf16(w, hi, lo);
            __nv_bfloat16* dst = g_W3e + (size_t)(n0 + i) * K2;
            dst[k0 + tx] = hi; dst[H_ + k0 + tx] = lo;
        }
        return;
    }
    blk -= PREP_WE;
    if (blk < PREP_CO) {
        int gidx = blk * 256 + tid;
        int layer = gidx / (H_ * N_);
        int idx   = gidx % (H_ * N_);
        int h = idx % H_;
        int n = idx / H_;
        int CLl = (layer <= 1) ? 64 : 32;

        float dt  = expf(log_dt[layer * H_ + h]);
        int pidx  = (layer * H_ + h) * N_ + n;
        float Are = -expf(log_A_real[pidx]);
        float Aim = A_imag[pidx];
        float dr = dt * Are, di = dt * Aim;
        float e  = expf(dr);
        float ar = e * cosf(di);
        float ai = e * sinf(di);
        float invA2 = 1.0f / (Are * Are + Aim * Aim);
        float dBr = ((ar - 1.0f) * Are + ai * Aim) * invA2;
        float dBi = (ai * Are - (ar - 1.0f) * Aim) * invA2;

        size_t c0idx = ((((size_t)layer * 2 + 0) * H_ + h) * N_ + n) * 2;
        size_t c1idx = ((((size_t)layer * 2 + 1) * H_ + h) * N_ + n) * 2;
        float c0r = C_ri[c0idx], c0i = C_ri[c0idx + 1];
        float c1r = C_ri[c1idx], c1i = C_ri[c1idx + 1];

        float eL = expf(CLl * dr);
        float* cf = g_CF + layer * CFSZ;
        cf[(0 * N_ + n) * H_ + h] = ar;
        cf[(1 * N_ + n) * H_ + h] = ai;
        cf[(2 * N_ + n) * H_ + h] = c0r * dBr - c0i * dBi;
        cf[(3 * N_ + n) * H_ + h] = c0r * dBi + c0i * dBr;
        cf[(4 * N_ + n) * H_ + h] = c1r * dBr - c1i * dBi;
        cf[(5 * N_ + n) * H_ + h] = c1r * dBi + c1i * dBr;
        cf[(6 * N_ + n) * H_ + h] = eL * cosf(CLl * di);
        cf[(7 * N_ + n) * H_ + h] = eL * sinf(CLl * di);
        return;
    }
    blk -= PREP_CO;
    {
        int row = blk;
        __shared__ float xs[8];
        if (tid < 8) xs[tid] = xr[(size_t)row * 8 + tid];
        __syncthreads();
        if (tid >= 192) return;
        __nv_bfloat16* dst = g_A3 + (size_t)row * K2;
#pragma unroll
        for (int p = tid; p < H_ / 2; p += 192) {
            int j = p * 2;
            float2 bv = *(const float2*)&b1[j];
            float s0 = bv.x, s1 = bv.y;
#pragma unroll
            for (int k = 0; k < 8; ++k) {
                float2 wv = *(const float2*)&w1[k * H_ + j];
                s0 = fmaf(xs[k], wv.x, s0);
                s1 = fmaf(xs[k], wv.y, s1);
            }
            float v0 = s0 / (1.0f + fabsf(s0));
            float v1 = s1 / (1.0f + fabsf(s1));
            __nv_bfloat16 h0, l0, h1, l1;
            split_bf16(v0, h0, l0);
            split_bf16(v1, h1, l1);
            *(__nv_bfloat162*)&dst[j]      = pack2(h0, h1);
            *(__nv_bfloat162*)&dst[H_ + j] = pack2(l0, l1);
        }
    }
}

// ---------------------------------------------------------------------------
// Scan pass 1: both directions, X read directly. Runtime CL.
// ---------------------------------------------------------------------------
__global__ void scan_pass1(const float* __restrict__ X, int L, int CL,
                           int layer) {
    int h   = blockIdx.x * 256 + threadIdx.x;
    int c   = blockIdx.y;
    int NCv = gridDim.y;
    int b   = blockIdx.z;
    int lo  = c * CL;
    const float* cf = g_CF + layer * CFSZ;

    float ar[N_], ai[N_], sr[N_], si[N_];
#pragma unroll
    for (int n = 0; n < N_; ++n) {
        ar[n] = cf[(0 * N_ + n) * H_ + h];
        ai[n] = cf[(1 * N_ + n) * H_ + h];
        sr[n] = 0.0f; si[n] = 0.0f;
    }
    const float* xp = X + ((size_t)b * L + lo) * H_ + h;
#pragma unroll 2
    for (int k = 0; k < CL; ++k) {
        float u = xp[(size_t)k * H_];
#pragma unroll
        for (int n = 0; n < N_; ++n) {
            float t = fmaf(ar[n], sr[n], fmaf(-ai[n], si[n], u));
            si[n] = fmaf(ar[n], si[n], ai[n] * sr[n]);
            sr[n] = t;
        }
    }
    float* f0 = g_S + (((size_t)(0 * BATCH + b) * NCv + c) * 32) * H_ + h;
#pragma unroll
    for (int n = 0; n < N_; ++n) {
        f0[(2 * n + 0) * H_] = sr[n];
        f0[(2 * n + 1) * H_] = si[n];
        sr[n] = 0.0f; si[n] = 0.0f;
    }
#pragma unroll 2
    for (int k = CL - 1; k >= 0; --k) {
        float u = xp[(size_t)k * H_];
#pragma unroll
        for (int n = 0; n < N_; ++n) {
            float t = fmaf(ar[n], sr[n], fmaf(-ai[n], si[n], u));
            si[n] = fmaf(ar[n], si[n], ai[n] * sr[n]);
            sr[n] = t;
        }
    }
    float* f1 = g_S + (((size_t)(1 * BATCH + b) * NCv + c) * 32) * H_ + h;
#pragma unroll
    for (int n = 0; n < N_; ++n) {
        f1[(2 * n + 0) * H_] = sr[n];
        f1[(2 * n + 1) * H_] = si[n];
    }
}

// ---------------------------------------------------------------------------
// Scan fix: tiled (8) batched loads, serial compose + stores.
// ---------------------------------------------------------------------------
__global__ void scan_fix(int NCv, int layer) {
    int idx = blockIdx.x * blockDim.x + threadIdx.x;
    int h   = idx % H_;
    int n   = (idx / H_) % N_;
    int b   = (idx / (H_ * N_)) % BATCH;
    int dir = idx / (H_ * N_ * BATCH);
    const float* cf = g_CF + layer * CFSZ;

    float aLr = cf[(6 * N_ + n) * H_ + h];
    float aLi = cf[(7 * N_ + n) * H_ + h];

    float* base = g_S + ((size_t)(dir * BATCH + b) * NCv * 32) * H_
                + (2 * n) * H_ + h;
    float accr = 0.0f, acci = 0.0f;
    for (int c0 = 0; c0 < NCv; c0 += 8) {
        float fr[8], fi[8];
#pragma unroll
        for (int i = 0; i < 8; ++i) {
            int cc = (dir == 0) ? (c0 + i) : (NCv - 1 - (c0 + i));
            float* p = base + (size_t)cc * 32 * H_;
            fr[i] = p[0];
            fi[i] = p[H_];
        }
#pragma unroll
        for (int i = 0; i < 8; ++i) {
            int cc = (dir == 0) ? (c0 + i) : (NCv - 1 - (c0 + i));
            float* p = base + (size_t)cc * 32 * H_;
            p[0]  = accr;
            p[H_] = acci;
            float t = aLr * accr - aLi * acci + fr[i];
            acci = aLr * acci + aLi * accr + fi[i];
            accr = t;
        }
    }
}

// ---------------------------------------------------------------------------
// Scan pass 2 (merged bwd+fwd). ybuf = dynamic smem (CL*1KB). Runtime CL.
// ---------------------------------------------------------------------------
__global__ void scan_pass2(const float* __restrict__ X,
                           const float* __restrict__ Dv,
                           int L, int CL, int Lout, int ds, int layer) {
    extern __shared__ float ybuf[];
    int h   = blockIdx.x * 256 + threadIdx.x;
    int c   = blockIdx.y;
    int NCv = gridDim.y;
    int b   = blockIdx.z;
    int tid = threadIdx.x;
    int lo  = c * CL;
    const float* cf = g_CF + layer * CFSZ;

    float ar[N_], ai[N_];
#pragma unroll
    for (int n = 0; n < N_; ++n) {
        ar[n] = cf[(0 * N_ + n) * H_ + h];
        ai[n] = cf[(1 * N_ + n) * H_ + h];
    }
    const float* xp = X + ((size_t)b * L + lo) * H_ + h;

    {
        float wr[N_], wi[N_], sr[N_], si[N_];
        const float* stp =
            g_S + (((size_t)(1 * BATCH + b) * NCv + c) * 32) * H_ + h;
#pragma unroll
        for (int n = 0; n < N_; ++n) {
            wr[n] = cf[(4 * N_ + n) * H_ + h];
            wi[n] = cf[(5 * N_ + n) * H_ + h];
            sr[n] = stp[(2 * n + 0) * H_];
            si[n] = stp[(2 * n + 1) * H_];
        }
#pragma unroll 2
        for (int k = CL - 1; k >= 0; --k) {
            int p = lo + k;
            if (!ds || !(p & 1)) {
                float a0 = 0.0f, a1 = 0.0f;
#pragma unroll
                for (int n = 0; n < N_; ++n) {
                    a0 = fmaf(wr[n], sr[n], a0);
                    a1 = fmaf(wi[n], si[n], a1);
                }
                ybuf[k * 256 + tid] = 2.0f * (a0 - a1);
            }
            float u = xp[(size_t)k * H_];
#pragma unroll
            for (int n = 0; n < N_; ++n) {
                float t = fmaf(ar[n], sr[n], fmaf(-ai[n], si[n], u));
                si[n] = fmaf(ar[n], si[n], ai[n] * sr[n]);
                sr[n] = t;
            }
        }
    }

    {
        float wr[N_], wi[N_], sr[N_], si[N_];
        const float* stp =
            g_S + (((size_t)(0 * BATCH + b) * NCv + c) * 32) * H_ + h;
#pragma unroll
        for (int n = 0; n < N_; ++n) {
            wr[n] = cf[(2 * N_ + n) * H_ + h];
            wi[n] = cf[(3 * N_ + n) * H_ + h];
            sr[n] = stp[(2 * n + 0) * H_];
            si[n] = stp[(2 * n + 1) * H_];
        }
        float Dh = Dv[h];
#pragma unroll 2
        for (int k = 0; k < CL; ++k) {
            float u = xp[(size_t)k * H_];
#pragma unroll
            for (int n = 0; n < N_; ++n) {
                float t = fmaf(ar[n], sr[n], fmaf(-ai[n], si[n], u));
                si[n] = fmaf(ar[n], si[n], ai[n] * sr[n]);
                sr[n] = t;
            }
            int l = lo + k;
            if (!ds || !(l & 1)) {
                float a0 = 0.0f, a1 = 0.0f;
#pragma unroll
                for (int n = 0; n < N_; ++n) {
                    a0 = fmaf(wr[n], sr[n], a0);
                    a1 = fmaf(wi[n], si[n], a1);
                }
                int lrow = ds ? (l >> 1) : l;
                size_t rr = (size_t)b * Lout + lrow;
                float yv = 2.0f * (a0 - a1) + ybuf[k * 256 + tid] + Dh * u;
                yv = 0.5f * yv * (1.0f + erff(yv * 0.70710678118654752f));
                __nv_bfloat16 hi, lo2; split_bf16(yv, hi, lo2);
                __nv_bfloat16* dst = g_A3 + rr * K2;
                dst[h] = hi; dst[H_ + h] = lo2;
            }
        }
    }
}

// ---------------------------------------------------------------------------
// GLU + residual + LayerNorm. 192 threads, float4. Split-K sum. (round-14)
// ---------------------------------------------------------------------------
__global__ void glu_ln_kernel(const float* __restrict__ V,
                              const float* __restrict__ V2,
                              const float* __restrict__ X,
                              const float* __restrict__ nw,
                              const float* __restrict__ nb,
                              float* __restrict__ out, int ds) {
    int row_out = blockIdx.x;
    int row_in  = ds ? row_out * 2 : row_out;
    const float4* v4  = (const float4*)(V  + (size_t)row_out * (2 * H_));
    const float4* v24 = (const float4*)(V2 + (size_t)row_out * (2 * H_));
    const float4* x4  = (const float4*)(X + (size_t)row_in * H_);
    int tid = threadIdx.x;

    float4 a = v4[tid];
    float4 g = v4[192 + tid];
    float4 a2 = v24[tid];
    float4 g2 = v24[192 + tid];
    a.x += a2.x; a.y += a2.y; a.z += a2.z; a.w += a2.w;
    g.x += g2.x; g.y += g2.y; g.z += g2.z; g.w += g2.w;
    float4 x = x4[tid];
    float4 z;
    z.x = a.x / (1.0f + __expf(-g.x)) + x.x;
    z.y = a.y / (1.0f + __expf(-g.y)) + x.y;
    z.z = a.z / (1.0f + __expf(-g.z)) + x.z;
    z.w = a.w / (1.0f + __expf(-g.w)) + x.w;
    float s = z.x + z.y + z.z + z.w;
    float q = z.x * z.x + z.y * z.y + z.z * z.z + z.w * z.w;

    __shared__ float sh[14];
    int lane = tid & 31, wid = tid >> 5;
#pragma unroll
    for (int o = 16; o; o >>= 1) {
        s += __shfl_xor_sync(0xffffffffu, s, o);
        q += __shfl_xor_sync(0xffffffffu, q, o);
    }
    if (lane == 0) { sh[wid] = s; sh[6 + wid] = q; }
    __syncthreads();
    if (tid == 0) {
        float S = 0.0f, Q = 0.0f;
#pragma unroll
        for (int i = 0; i < 6; ++i) { S += sh[i]; Q += sh[6 + i]; }
        float mu = S * (1.0f / H_);
        float var = Q * (1.0f / H_) - mu * mu;
        sh[12] = mu;
        sh[13] = rsqrtf(var + 1e-5f);
    }
    __syncthreads();
    float mu = sh[12], inv = sh[13];
    float4 w = ((const float4*)nw)[tid];
    float4 bb = ((const float4*)nb)[tid];
    float4 o;
    o.x = (z.x - mu) * inv * w.x + bb.x;
    o.y = (z.y - mu) * inv * w.y + bb.y;
    o.z = (z.z - mu) * inv * w.z + bb.z;
    o.w = (z.w - mu) * inv * w.w + bb.w;
    ((float4*)(out + (size_t)row_out * H_))[tid] = o;
}

// ---------------------------------------------------------------------------
// Head
// ---------------------------------------------------------------------------
__global__ void head_kernel(const float* __restrict__ X,
                            const float* __restrict__ W,
                            const float* __restrict__ bb,
                            float* __restrict__ out) {
    int row = blockIdx.x;
    __shared__ float xs[H_];
    for (int j = threadIdx.x; j < H_; j += blockDim.x)
        xs[j] = X[(size_t)row * H_ + j];
    __syncthreads();
    int d = threadIdx.x;
    if (d < NOUTS) {
        float sum = bb[d];
#pragma unroll 4
        for (int k = 0; k < H_; ++k)
            sum = fmaf(xs[k], W[k * NOUTS + d], sum);
        out[(size_t)row * NOUTS + d] = sum;
    }
}

// ---------------------------------------------------------------------------
extern "C" void kernel_launch(void* const* d_in, const int* in_sizes, int n_in,
                              void* d_out, int out_size) {
    const float* x_raw      = (const float*)d_in[1];
    const float* enc_w1     = (const float*)d_in[3];
    const float* enc_b1     = (const float*)d_in[4];
    const float* enc_w2     = (const float*)d_in[5];
    const float* enc_b2     = (const float*)d_in[6];
    const float* log_dt     = (const float*)d_in[7];
    const float* log_A_real = (const float*)d_in[8];
    const float* A_imag     = (const float*)d_in[9];
    const float* C_ri       = (const float*)d_in[10];
    const float* Dv         = (const float*)d_in[11];
    const float* out_w      = (const float*)d_in[12];
    const float* out_b      = (const float*)d_in[13];
    const float* norm_w     = (const float*)d_in[14];
    const float* norm_b     = (const float*)d_in[15];
    const float* wout_w     = (const float*)d_in[16];
    const float* wout_b     = (const float*)d_in[17];

    float *gA, *gB, *gV, *gV2;
    cudaGetSymbolAddress((void**)&gA,  g_A);
    cudaGetSymbolAddress((void**)&gB,  g_Bf);
    cudaGetSymbolAddress((void**)&gV,  g_V);
    cudaGetSymbolAddress((void**)&gV2, g_V2);
    __nv_bfloat16 *gA3, *gW3, *gW3e;
    cudaGetSymbolAddress((void**)&gA3,  g_A3);
    cudaGetSymbolAddress((void**)&gW3,  g_W3);
    cudaGetSymbolAddress((void**)&gW3e, g_W3e);

    cudaFuncSetAttribute(hmma_gemm_kernel,
                         cudaFuncAttributeMaxDynamicSharedMemorySize, GSMEM);
    cudaFuncSetAttribute(scan_pass2,
                         cudaFuncAttributeMaxDynamicSharedMemorySize, 65536);

    prep_kernel<<<PREP_WL + PREP_WE + PREP_CO + MROWS, 256>>>(
        out_w, enc_w2, log_dt, log_A_real, A_imag, C_ri,
        x_raw, enc_w1, enc_b1);

    hmma_gemm_kernel<<<dim3(H_ / 128, MROWS / 128, 1), 256, GSMEM>>>(
        gA3, gW3e, enc_b2, gA, gV2, H_, 1);

    int Lcur = LMAX;
    float* cur = gA;
    float* nxt = gB;
    for (int i = 0; i < NLAYERS; ++i) {
        int ds   = (i <= 2) ? 1 : 0;
        int Lout = ds ? Lcur / 2 : Lcur;
        int CL   = (i <= 1) ? 64 : 32;
        int NCv  = Lcur / CL;
        int Mout = BATCH * Lout;
        int ysm  = CL * 256 * 4;

        scan_pass1<<<dim3(3, NCv, BATCH), 256>>>(cur, Lcur, CL, i);
        scan_fix<<<(2 * BATCH * H_ * N_) / 256, 256>>>(NCv, i);
        scan_pass2<<<dim3(3, NCv, BATCH), 256, ysm>>>(cur, Dv + i * H_,
                                                      Lcur, CL, Lout, ds, i);
        dim3 ggrid(NT_GLU, Mout / 128, 2);
        hmma_gemm_kernel<<<ggrid, 256, GSMEM>>>(
            gA3, gW3 + (size_t)i * 2 * H_ * K2, out_b + (size_t)i * 2 * H_,
            gV, gV2, 2 * H_, 2);
        glu_ln_kernel<<<Mout, 192>>>(gV, gV2, cur, norm_w + i * H_,
                                     norm_b + i * H_, nxt, ds);
        Lcur = Lout;
        float* tmp = cur; cur = nxt; nxt = tmp;
    }

    head_kernel<<<BATCH * Lcur, 128>>>(cur, wout_w, wout_b, (float*)d_out);
}

// round 17
// speedup vs baseline: 1.5873x; 1.0630x over previous
#include <cuda_runtime.h>
#include <cuda_bf16.h>
#include <math.h>
#include <stdint.h>

#define H_ 768
#define N_ 16
#define NLAYERS 6
#define NOUTS 38
#define BATCH 8
#define LMAX 2048
#define CL_ 32
#define K2 1536          // stored fat-K width; logical K is 2304
#define NCH 36
#define NSTAGE 3
#define STAGE_BYTES 32768
#define GSMEM (NSTAGE * STAGE_BYTES)
#define CFSZ (8*N_*H_)
#define MROWS (BATCH*LMAX)
#define NT_GLU 12

__device__ float g_A [MROWS*H_];
__device__ float g_Bf[MROWS*H_];
__device__ float g_V [MROWS*2*H_];
__device__ float g_V2[MROWS*2*H_];
__device__ float g_S [(size_t)2*BATCH*64*2*N_*H_];   // NCv <= 64
__device__ float g_CF[NLAYERS*CFSZ];
__device__ __nv_bfloat16 g_A3 [(size_t)MROWS*K2];
__device__ __nv_bfloat16 g_W3 [(size_t)NLAYERS*2*H_*K2];
__device__ __nv_bfloat16 g_W3e[(size_t)H_*K2];

__device__ __forceinline__ int mapA(int c) { return (c < 24) ? c : c - 24; }
__device__ __forceinline__ int mapB(int c) { return (c < 12) ? c : c - 12; }

// ---------------------------------------------------------------------------
// helpers
// ---------------------------------------------------------------------------
__device__ __forceinline__ uint32_t smem_u32(const void* p) {
    uint32_t a;
    asm("{ .reg .u64 t; cvta.to.shared.u64 t, %1; cvt.u32.u64 %0, t; }"
        : "=r"(a) : "l"(p));
    return a;
}
__device__ __forceinline__ void ldm4(uint32_t* r, uint32_t addr) {
    asm volatile("ldmatrix.sync.aligned.m8n8.x4.shared.b16 {%0,%1,%2,%3}, [%4];"
                 : "=r"(r[0]), "=r"(r[1]), "=r"(r[2]), "=r"(r[3]) : "r"(addr));
}
__device__ __forceinline__ void mma16816(float* c, const uint32_t* a,
                                         const uint32_t* b) {
    asm volatile(
        "mma.sync.aligned.m16n8k16.row.col.f32.bf16.bf16.f32 "
        "{%0,%1,%2,%3}, {%4,%5,%6,%7}, {%8,%9}, {%0,%1,%2,%3};"
        : "+f"(c[0]), "+f"(c[1]), "+f"(c[2]), "+f"(c[3])
        : "r"(a[0]), "r"(a[1]), "r"(a[2]), "r"(a[3]), "r"(b[0]), "r"(b[1]));
}
__device__ __forceinline__ void cp16(uint32_t saddr, const void* g) {
    asm volatile("cp.async.cg.shared.global [%0], [%1], 16;"
                 :: "r"(saddr), "l"(g));
}
__device__ __forceinline__ void cp_commit() {
    asm volatile("cp.async.commit_group;" ::: "memory");
}
template <int Nw>
__device__ __forceinline__ void cp_wait() {
    asm volatile("cp.async.wait_group %0;" :: "n"(Nw) : "memory");
}
__device__ __forceinline__ void split_bf16(float x, __nv_bfloat16& hi,
                                           __nv_bfloat16& lo) {
    hi = __float2bfloat16(x);
    lo = __float2bfloat16(x - __bfloat162float(hi));
}
__device__ __forceinline__ __nv_bfloat162 pack2(__nv_bfloat16 a,
                                                __nv_bfloat16 b) {
    __nv_bfloat162 r; r.x = a; r.y = b; return r;
}

// ---------------------------------------------------------------------------
// HMMA bf16 GEMM over logical K=2304, deduped 2-segment storage.
// ---------------------------------------------------------------------------
__global__ void __launch_bounds__(256, 2)
hmma_gemm_kernel(const __nv_bfloat16* __restrict__ A3,
                 const __nv_bfloat16* __restrict__ B3,
                 const float* __restrict__ bias,
                 float* __restrict__ C, float* __restrict__ C2,
                 int Ncols, int nsplit) {
    extern __shared__ __align__(128) char smem[];
    const uint32_t sbase = smem_u32(smem);

    const int tid  = threadIdx.x;
    const int wid  = tid >> 5;
    const int lane = tid & 31;
    const int warp_m = wid >> 2;
    const int warp_n = wid & 3;
    const int m_base = warp_m * 64;
    const int n_base = warp_n * 32;

    const int kz    = (int)blockIdx.z;
    const int nch   = NCH / nsplit;
    const int kbase = kz * nch;
    float* Cout = (kz == 0) ? C : C2;
    const bool addb = (kz == 0);

    const int m0 = blockIdx.y * 128;
    const int n0 = blockIdx.x * 128;
    const __nv_bfloat16* Ab = A3 + (size_t)m0 * K2;
    const __nv_bfloat16* Bb = B3 + (size_t)n0 * K2;

    const int st_row = tid >> 3;
    const int st_seg = tid & 7;
    uint32_t st_off[4];
#pragma unroll
    for (int i = 0; i < 4; ++i) {
        int r = st_row + i * 32;
        st_off[i] = (uint32_t)(r * 128 + ((st_seg ^ (r & 7)) * 16));
    }

    int rA[4], xA[4];
#pragma unroll
    for (int mt = 0; mt < 4; ++mt) {
        rA[mt] = m_base + mt * 16 + (lane & 15);
        xA[mt] = rA[mt] & 7;
    }
    const int uhA = lane >> 4;
    int rB[2], xB[2];
#pragma unroll
    for (int nt2 = 0; nt2 < 2; ++nt2) {
        rB[nt2] = n_base + nt2 * 16 + ((lane >> 4) << 3) + (lane & 7);
        xB[nt2] = rB[nt2] & 7;
    }
    const int uhB = (lane >> 3) & 1;

    float acc[4][4][4];
#pragma unroll
    for (int mt = 0; mt < 4; ++mt)
#pragma unroll
        for (int nt = 0; nt < 4; ++nt)
#pragma unroll
            for (int e = 0; e < 4; ++e) acc[mt][nt][e] = 0.0f;

#pragma unroll
    for (int s = 0; s < NSTAGE - 1; ++s) {
        uint32_t sa = sbase + s * STAGE_BYTES;
        uint32_t sb = sa + 16384;
        int lcA = mapA(kbase + s), lcB = mapB(kbase + s);
#pragma unroll
        for (int i = 0; i < 4; ++i) {
            int r = st_row + i * 32;
            cp16(sa + st_off[i], Ab + (size_t)r * K2 + lcA * 64 + st_seg * 8);
            cp16(sb + st_off[i], Bb + (size_t)r * K2 + lcB * 64 + st_seg * 8);
        }
        cp_commit();
    }

    uint32_t cur_s = sbase;
    uint32_t pf_s  = sbase + (NSTAGE - 1) * STAGE_BYTES;
    for (int c = 0; c < nch; ++c) {
        cp_wait<NSTAGE - 2>();
        __syncthreads();
        int pf = c + NSTAGE - 1;
        if (pf < nch) {
            uint32_t sa = pf_s;
            uint32_t sb = sa + 16384;
            int lcA = mapA(kbase + pf), lcB = mapB(kbase + pf);
#pragma unroll
            for (int i = 0; i < 4; ++i) {
                int r = st_row + i * 32;
                cp16(sa + st_off[i], Ab + (size_t)r * K2 + lcA * 64 + st_seg * 8);
                cp16(sb + st_off[i], Bb + (size_t)r * K2 + lcB * 64 + st_seg * 8);
            }
        }
        cp_commit();

        uint32_t sa = cur_s;
        uint32_t sb = sa + 16384;
#pragma unroll
        for (int kk = 0; kk < 4; ++kk) {
            uint32_t af[4][4], bf[2][4];
#pragma unroll
            for (int mt = 0; mt < 4; ++mt)
                ldm4(af[mt], sa + (uint32_t)(rA[mt] * 128 +
                             (((kk * 2 + uhA) ^ xA[mt]) * 16)));
#pragma unroll
            for (int nt2 = 0; nt2 < 2; ++nt2)
                ldm4(bf[nt2], sb + (uint32_t)(rB[nt2] * 128 +
                              (((kk * 2 + uhB) ^ xB[nt2]) * 16)));
#pragma unroll
            for (int mt = 0; mt < 4; ++mt)
#pragma unroll
                for (int nt = 0; nt < 4; ++nt)
                    mma16816(acc[mt][nt], af[mt], &bf[nt >> 1][(nt & 1) * 2]);
        }
        cur_s += STAGE_BYTES;
        if (cur_s == sbase + NSTAGE * STAGE_BYTES) cur_s = sbase;
        pf_s += STAGE_BYTES;
        if (pf_s == sbase + NSTAGE * STAGE_BYTES) pf_s = sbase;
    }

    const int gr = lane >> 2;
    const int gc = (lane & 3) * 2;
#pragma unroll
    for (int nt = 0; nt < 4; ++nt) {
        int ncol = n0 + n_base + nt * 8 + gc;
        float b0 = addb ? bias[ncol] : 0.0f;
        float b1 = addb ? bias[ncol + 1] : 0.0f;
#pragma unroll
        for (int mt = 0; mt < 4; ++mt) {
            int mr = m0 + m_base + mt * 16 + gr;
            float2 v0 = make_float2(acc[mt][nt][0] + b0, acc[mt][nt][1] + b1);
            float2 v1 = make_float2(acc[mt][nt][2] + b0, acc[mt][nt][3] + b1);
            *(float2*)&Cout[(size_t)mr * Ncols + ncol] = v0;
            *(float2*)&Cout[(size_t)(mr + 8) * Ncols + ncol] = v1;
        }
    }
}

// ---------------------------------------------------------------------------
// Unified prep kernel (wconv_layers | wconv_enc | coef | enc1)
// ---------------------------------------------------------------------------
#define PREP_WL ((NLAYERS * 2 * H_ * (H_ / 2)) / 256)
#define PREP_WE ((H_ / 32) * (H_ / 32))
#define PREP_CO ((H_ * N_ * NLAYERS) / 256)

__global__ void prep_kernel(const float* __restrict__ out_w,
                            const float* __restrict__ w2,
                            const float* __restrict__ log_dt,
                            const float* __restrict__ log_A_real,
                            const float* __restrict__ A_imag,
                            const float* __restrict__ C_ri,
                            const float* __restrict__ xr,
                            const float* __restrict__ w1,
                            const float* __restrict__ b1) {
    int blk = blockIdx.x;
    int tid = threadIdx.x;

    if (blk < PREP_WL) {
        size_t idx = (size_t)blk * 256 + tid;
        int kp = idx % (H_ / 2);
        size_t nr = idx / (H_ / 2);
        int j = kp * 2;
        float2 w = *(const float2*)&out_w[nr * H_ + j];
        __nv_bfloat16 h0, l0, h1, l1;
        split_bf16(w.x, h0, l0);
        split_bf16(w.y, h1, l1);
        __nv_bfloat16* dst = g_W3 + nr * K2;
        *(__nv_bfloat162*)&dst[j]      = pack2(h0, h1);
        *(__nv_bfloat162*)&dst[H_ + j] = pack2(l0, l1);
        return;
    }
    blk -= PREP_WL;
    if (blk < PREP_WE) {
        __shared__ float t[32][33];
        int bx = blk % (H_ / 32), by = blk / (H_ / 32);
        int k0 = by * 32, n0 = bx * 32;
        int tx = tid & 31, ty = tid >> 5;
#pragma unroll
        for (int i = ty; i < 32; i += 8)
            t[i][tx] = w2[(size_t)(k0 + i) * H_ + n0 + tx];
        __syncthreads();
#pragma unroll
        for (int i = ty; i < 32; i += 8) {
            float w = t[tx][i];
            __nv_bfloat16 hi, lo; split_bf16(w, hi, lo);
            __nv_bfloat16* dst = g_W3e + (size_t)(n0 + i) * K2;
            dst[k0 + tx] = hi; dst[H_ + k0 + tx] = lo;
        }
        return;
    }
    blk -= PREP_WE;
    if (blk < PREP_CO) {
        int gidx = blk * 256 + tid;
        int layer = gidx / (H_ * N_);
        int idx   = gidx % (H_ * N_);
        int h = idx % H_;
        int n = idx / H_;

        float dt  = expf(log_dt[layer * H_ + h]);
        int pidx  = (layer * H_ + h) * N_ + n;
        float Are = -expf(log_A_real[pidx]);
        float Aim = A_imag[pidx];
        float dr = dt * Are, di = dt * Aim;
        float e  = expf(dr);
        float ar = e * cosf(di);
        float ai = e * sinf(di);
        float invA2 = 1.0f / (Are * Are + Aim * Aim);
        float dBr = ((ar - 1.0f) * Are + ai * Aim) * invA2;
        float dBi = (ai * Are - (ar - 1.0f) * Aim) * invA2;

        size_t c0idx = ((((size_t)layer * 2 + 0) * H_ + h) * N_ + n) * 2;
        size_t c1idx = ((((size_t)layer * 2 + 1) * H_ + h) * N_ + n) * 2;
        float c0r = C_ri[c0idx], c0i = C_ri[c0idx + 1];
        float c1r = C_ri[c1idx], c1i = C_ri[c1idx + 1];

        float eL = expf(CL_ * dr);
        float* cf = g_CF + layer * CFSZ;
        cf[(0 * N_ + n) * H_ + h] = ar;
        cf[(1 * N_ + n) * H_ + h] = ai;
        cf[(2 * N_ + n) * H_ + h] = c0r * dBr - c0i * dBi;
        cf[(3 * N_ + n) * H_ + h] = c0r * dBi + c0i * dBr;
        cf[(4 * N_ + n) * H_ + h] = c1r * dBr - c1i * dBi;
        cf[(5 * N_ + n) * H_ + h] = c1r * dBi + c1i * dBr;
        cf[(6 * N_ + n) * H_ + h] = eL * cosf(CL_ * di);
        cf[(7 * N_ + n) * H_ + h] = eL * sinf(CL_ * di);
        return;
    }
    blk -= PREP_CO;
    {
        int row = blk;
        __shared__ float xs[8];
        if (tid < 8) xs[tid] = xr[(size_t)row * 8 + tid];
        __syncthreads();
        if (tid >= 192) return;
        __nv_bfloat16* dst = g_A3 + (size_t)row * K2;
#pragma unroll
        for (int p = tid; p < H_ / 2; p += 192) {
            int j = p * 2;
            float2 bv = *(const float2*)&b1[j];
            float s0 = bv.x, s1 = bv.y;
#pragma unroll
            for (int k = 0; k < 8; ++k) {
                float2 wv = *(const float2*)&w1[k * H_ + j];
                s0 = fmaf(xs[k], wv.x, s0);
                s1 = fmaf(xs[k], wv.y, s1);
            }
            float v0 = s0 / (1.0f + fabsf(s0));
            float v1 = s1 / (1.0f + fabsf(s1));
            __nv_bfloat16 h0, l0, h1, l1;
            split_bf16(v0, h0, l0);
            split_bf16(v1, h1, l1);
            *(__nv_bfloat162*)&dst[j]      = pack2(h0, h1);
            *(__nv_bfloat162*)&dst[H_ + j] = pack2(l0, l1);
        }
    }
}

// ---------------------------------------------------------------------------
// Scan pass 1: both directions in one block, X staged once in smem (CL_=32).
// grid (3, NCv, B), block 256. Column-private xbuf -> no syncs needed.
// ---------------------------------------------------------------------------
__global__ void scan_pass1(const float* __restrict__ X, int L, int layer) {
    __shared__ float xbuf[CL_][256];
    int h   = blockIdx.x * 256 + threadIdx.x;
    int c   = blockIdx.y;
    int NCv = gridDim.y;
    int b   = blockIdx.z;
    int tid = threadIdx.x;
    int lo  = c * CL_;
    const float* cf = g_CF + layer * CFSZ;

    const float* xp = X + ((size_t)b * L + lo) * H_ + h;
#pragma unroll
    for (int k = 0; k < CL_; ++k)
        xbuf[k][tid] = xp[(size_t)k * H_];

    float ar[N_], ai[N_], sr[N_], si[N_];
#pragma unroll
    for (int n = 0; n < N_; ++n) {
        ar[n] = cf[(0 * N_ + n) * H_ + h];
        ai[n] = cf[(1 * N_ + n) * H_ + h];
        sr[n] = 0.0f; si[n] = 0.0f;
    }
#pragma unroll 2
    for (int k = 0; k < CL_; ++k) {
        float u = xbuf[k][tid];
#pragma unroll
        for (int n = 0; n < N_; ++n) {
            float t = fmaf(ar[n], sr[n], fmaf(-ai[n], si[n], u));
            si[n] = fmaf(ar[n], si[n], ai[n] * sr[n]);
            sr[n] = t;
        }
    }
    float* f0 = g_S + (((size_t)(0 * BATCH + b) * NCv + c) * 32) * H_ + h;
#pragma unroll
    for (int n = 0; n < N_; ++n) {
        f0[(2 * n + 0) * H_] = sr[n];
        f0[(2 * n + 1) * H_] = si[n];
        sr[n] = 0.0f; si[n] = 0.0f;
    }
#pragma unroll 2
    for (int k = CL_ - 1; k >= 0; --k) {
        float u = xbuf[k][tid];
#pragma unroll
        for (int n = 0; n < N_; ++n) {
            float t = fmaf(ar[n], sr[n], fmaf(-ai[n], si[n], u));
            si[n] = fmaf(ar[n], si[n], ai[n] * sr[n]);
            sr[n] = t;
        }
    }
    float* f1 = g_S + (((size_t)(1 * BATCH + b) * NCv + c) * 32) * H_ + h;
#pragma unroll
    for (int n = 0; n < N_; ++n) {
        f1[(2 * n + 0) * H_] = sr[n];
        f1[(2 * n + 1) * H_] = si[n];
    }
}

// ---------------------------------------------------------------------------
// Scan fix: tiled (8) batched loads, serial compose + stores. NCv in 8..64.
// ---------------------------------------------------------------------------
__global__ void scan_fix(int NCv, int layer) {
    int idx = blockIdx.x * blockDim.x + threadIdx.x;
    int h   = idx % H_;
    int n   = (idx / H_) % N_;
    int b   = (idx / (H_ * N_)) % BATCH;
    int dir = idx / (H_ * N_ * BATCH);
    const float* cf = g_CF + layer * CFSZ;

    float aLr = cf[(6 * N_ + n) * H_ + h];
    float aLi = cf[(7 * N_ + n) * H_ + h];

    float* base = g_S + ((size_t)(dir * BATCH + b) * NCv * 32) * H_
                + (2 * n) * H_ + h;
    float accr = 0.0f, acci = 0.0f;
    for (int c0 = 0; c0 < NCv; c0 += 8) {
        float fr[8], fi[8];
#pragma unroll
        for (int i = 0; i < 8; ++i) {
            int cc = (dir == 0) ? (c0 + i) : (NCv - 1 - (c0 + i));
            float* p = base + (size_t)cc * 32 * H_;
            fr[i] = p[0];
            fi[i] = p[H_];
        }
#pragma unroll
        for (int i = 0; i < 8; ++i) {
            int cc = (dir == 0) ? (c0 + i) : (NCv - 1 - (c0 + i));
            float* p = base + (size_t)cc * 32 * H_;
            p[0]  = accr;
            p[H_] = acci;
            float t = aLr * accr - aLi * acci + fr[i];
            acci = aLr * acci + aLi * accr + fi[i];
            accr = t;
        }
    }
}

// ---------------------------------------------------------------------------
// Scan pass 2 (merged bwd+fwd). ybuf/xbuf column-private static smem (CL_=32).
// ---------------------------------------------------------------------------
__global__ void scan_pass2(const float* __restrict__ X,
                           const float* __restrict__ Dv,
                           int L, int Lout, int ds, int layer) {
    __shared__ float ybuf[CL_][256];
    __shared__ float xbuf[CL_][256];
    int h   = blockIdx.x * 256 + threadIdx.x;
    int c   = blockIdx.y;
    int NCv = gridDim.y;
    int b   = blockIdx.z;
    int tid = threadIdx.x;
    int lo  = c * CL_;
    const float* cf = g_CF + layer * CFSZ;

    const float* xp0 = X + ((size_t)b * L + lo) * H_ + h;
#pragma unroll
    for (int k = 0; k < CL_; ++k)
        xbuf[k][tid] = xp0[(size_t)k * H_];

    float ar[N_], ai[N_];
#pragma unroll
    for (int n = 0; n < N_; ++n) {
        ar[n] = cf[(0 * N_ + n) * H_ + h];
        ai[n] = cf[(1 * N_ + n) * H_ + h];
    }

    {
        float wr[N_], wi[N_], sr[N_], si[N_];
        const float* stp =
            g_S + (((size_t)(1 * BATCH + b) * NCv + c) * 32) * H_ + h;
#pragma unroll
        for (int n = 0; n < N_; ++n) {
            wr[n] = cf[(4 * N_ + n) * H_ + h];
            wi[n] = cf[(5 * N_ + n) * H_ + h];
            sr[n] = stp[(2 * n + 0) * H_];
            si[n] = stp[(2 * n + 1) * H_];
        }
#pragma unroll 2
        for (int k = CL_ - 1; k >= 0; --k) {
            int p = lo + k;
            if (!ds || !(p & 1)) {
                float a0 = 0.0f, a1 = 0.0f;
#pragma unroll
                for (int n = 0; n < N_; ++n) {
                    a0 = fmaf(wr[n], sr[n], a0);
                    a1 = fmaf(wi[n], si[n], a1);
                }
                ybuf[k][tid] = 2.0f * (a0 - a1);
            }
            float u = xbuf[k][tid];
#pragma unroll
            for (int n = 0; n < N_; ++n) {
                float t = fmaf(ar[n], sr[n], fmaf(-ai[n], si[n], u));
                si[n] = fmaf(ar[n], si[n], ai[n] * sr[n]);
                sr[n] = t;
            }
        }
    }

    {
        float wr[N_], wi[N_], sr[N_], si[N_];
        const float* stp =
            g_S + (((size_t)(0 * BATCH + b) * NCv + c) * 32) * H_ + h;
#pragma unroll
        for (int n = 0; n < N_; ++n) {
            wr[n] = cf[(2 * N_ + n) * H_ + h];
            wi[n] = cf[(3 * N_ + n) * H_ + h];
            sr[n] = stp[(2 * n + 0) * H_];
            si[n] = stp[(2 * n + 1) * H_];
        }
        float Dh = Dv[h];
#pragma unroll 2
        for (int k = 0; k < CL_; ++k) {
            float u = xbuf[k][tid];
#pragma unroll
            for (int n = 0; n < N_; ++n) {
                float t = fmaf(ar[n], sr[n], fmaf(-ai[n], si[n], u));
                si[n] = fmaf(ar[n], si[n], ai[n] * sr[n]);
                sr[n] = t;
            }
            int l = lo + k;
            if (!ds || !(l & 1)) {
                float a0 = 0.0f, a1 = 0.0f;
#pragma unroll
                for (int n = 0; n < N_; ++n) {
                    a0 = fmaf(wr[n], sr[n], a0);
                    a1 = fmaf(wi[n], si[n], a1);
                }
                int lrow = ds ? (l >> 1) : l;
                size_t rr = (size_t)b * Lout + lrow;
                float yv = 2.0f * (a0 - a1) + ybuf[k][tid] + Dh * u;
                yv = 0.5f * yv * (1.0f + erff(yv * 0.70710678118654752f));
                __nv_bfloat16 hi, lo2; split_bf16(yv, hi, lo2);
                __nv_bfloat16* dst = g_A3 + rr * K2;
                dst[h] = hi; dst[H_ + h] = lo2;
            }
        }
    }
}

// ---------------------------------------------------------------------------
// GLU + residual + LayerNorm. 192 threads, float4. Split-K sum.
// ---------------------------------------------------------------------------
__global__ void glu_ln_kernel(const float* __restrict__ V,
                              const float* __restrict__ V2,
                              const float* __restrict__ X,
                              const float* __restrict__ nw,
                              const float* __restrict__ nb,
                              float* __restrict__ out, int ds) {
    int row_out = blockIdx.x;
    int row_in  = ds ? row_out * 2 : row_out;
    const float4* v4  = (const float4*)(V  + (size_t)row_out * (2 * H_));
    const float4* v24 = (const float4*)(V2 + (size_t)row_out * (2 * H_));
    const float4* x4  = (const float4*)(X + (size_t)row_in * H_);
    int tid = threadIdx.x;

    float4 a = v4[tid];
    float4 g = v4[192 + tid];
    float4 a2 = v24[tid];
    float4 g2 = v24[192 + tid];
    a.x += a2.x; a.y += a2.y; a.z += a2.z; a.w += a2.w;
    g.x += g2.x; g.y += g2.y; g.z += g2.z; g.w += g2.w;
    float4 x = x4[tid];
    float4 z;
    z.x = a.x / (1.0f + __expf(-g.x)) + x.x;
    z.y = a.y / (1.0f + __expf(-g.y)) + x.y;
    z.z = a.z / (1.0f + __expf(-g.z)) + x.z;
    z.w = a.w / (1.0f + __expf(-g.w)) + x.w;
    float s = z.x + z.y + z.z + z.w;
    float q = z.x * z.x + z.y * z.y + z.z * z.z + z.w * z.w;

    __shared__ float sh[14];
    int lane = tid & 31, wid = tid >> 5;
#pragma unroll
    for (int o = 16; o; o >>= 1) {
        s += __shfl_xor_sync(0xffffffffu, s, o);
        q += __shfl_xor_sync(0xffffffffu, q, o);
    }
    if (lane == 0) { sh[wid] = s; sh[6 + wid] = q; }
    __syncthreads();
    if (tid == 0) {
        float S = 0.0f, Q = 0.0f;
#pragma unroll
        for (int i = 0; i < 6; ++i) { S += sh[i]; Q += sh[6 + i]; }
        float mu = S * (1.0f / H_);
        float var = Q * (1.0f / H_) - mu * mu;
        sh[12] = mu;
        sh[13] = rsqrtf(var + 1e-5f);
    }
    __syncthreads();
    float mu = sh[12], inv = sh[13];
    float4 w = ((const float4*)nw)[tid];
    float4 bb = ((const float4*)nb)[tid];
    float4 o;
    o.x = (z.x - mu) * inv * w.x + bb.x;
    o.y = (z.y - mu) * inv * w.y + bb.y;
    o.z = (z.z - mu) * inv * w.z + bb.z;
    o.w = (z.w - mu) * inv * w.w + bb.w;
    ((float4*)(out + (size_t)row_out * H_))[tid] = o;
}

// ---------------------------------------------------------------------------
// Head
// ---------------------------------------------------------------------------
__global__ void head_kernel(const float* __restrict__ X,
                            const float* __restrict__ W,
                            const float* __restrict__ bb,
                            float* __restrict__ out) {
    int row = blockIdx.x;
    __shared__ float xs[H_];
    for (int j = threadIdx.x; j < H_; j += blockDim.x)
        xs[j] = X[(size_t)row * H_ + j];
    __syncthreads();
    int d = threadIdx.x;
    if (d < NOUTS) {
        float sum = bb[d];
#pragma unroll 4
        for (int k = 0; k < H_; ++k)
            sum = fmaf(xs[k], W[k * NOUTS + d], sum);
        out[(size_t)row * NOUTS + d] = sum;
    }
}

// ---------------------------------------------------------------------------
extern "C" void kernel_launch(void* const* d_in, const int* in_sizes, int n_in,
                              void* d_out, int out_size) {
    const float* x_raw      = (const float*)d_in[1];
    const float* enc_w1     = (const float*)d_in[3];
    const float* enc_b1     = (const float*)d_in[4];
    const float* enc_w2     = (const float*)d_in[5];
    const float* enc_b2     = (const float*)d_in[6];
    const float* log_dt     = (const float*)d_in[7];
    const float* log_A_real = (const float*)d_in[8];
    const float* A_imag     = (const float*)d_in[9];
    const float* C_ri       = (const float*)d_in[10];
    const float* Dv         = (const float*)d_in[11];
    const float* out_w      = (const float*)d_in[12];
    const float* out_b      = (const float*)d_in[13];
    const float* norm_w     = (const float*)d_in[14];
    const float* norm_b     = (const float*)d_in[15];
    const float* wout_w     = (const float*)d_in[16];
    const float* wout_b     = (const float*)d_in[17];

    float *gA, *gB, *gV, *gV2;
    cudaGetSymbolAddress((void**)&gA,  g_A);
    cudaGetSymbolAddress((void**)&gB,  g_Bf);
    cudaGetSymbolAddress((void**)&gV,  g_V);
    cudaGetSymbolAddress((void**)&gV2, g_V2);
    __nv_bfloat16 *gA3, *gW3, *gW3e;
    cudaGetSymbolAddress((void**)&gA3,  g_A3);
    cudaGetSymbolAddress((void**)&gW3,  g_W3);
    cudaGetSymbolAddress((void**)&gW3e, g_W3e);

    cudaFuncSetAttribute(hmma_gemm_kernel,
                         cudaFuncAttributeMaxDynamicSharedMemorySize, GSMEM);

    prep_kernel<<<PREP_WL + PREP_WE + PREP_CO + MROWS, 256>>>(
        out_w, enc_w2, log_dt, log_A_real, A_imag, C_ri,
        x_raw, enc_w1, enc_b1);

    hmma_gemm_kernel<<<dim3(H_ / 128, MROWS / 128, 1), 256, GSMEM>>>(
        gA3, gW3e, enc_b2, gA, gV2, H_, 1);

    int Lcur = LMAX;
    float* cur = gA;
    float* nxt = gB;
    for (int i = 0; i < NLAYERS; ++i) {
        int ds   = (i <= 2) ? 1 : 0;
        int Lout = ds ? Lcur / 2 : Lcur;
        int NCv  = Lcur / CL_;
        int Mout = BATCH * Lout;

        scan_pass1<<<dim3(3, NCv, BATCH), 256>>>(cur, Lcur, i);
        scan_fix<<<(2 * BATCH * H_ * N_) / 256, 256>>>(NCv, i);
        scan_pass2<<<dim3(3, NCv, BATCH), 256>>>(cur, Dv + i * H_,
                                                 Lcur, Lout, ds, i);
        dim3 ggrid(NT_GLU, Mout / 128, 2);
        hmma_gemm_kernel<<<ggrid, 256, GSMEM>>>(
            gA3, gW3 + (size_t)i * 2 * H_ * K2, out_b + (size_t)i * 2 * H_,
            gV, gV2, 2 * H_, 2);
        glu_ln_kernel<<<Mout, 192>>>(gV, gV2, cur, norm_w + i * H_,
                                     norm_b + i * H_, nxt, ds);
        Lcur = Lout;
        float* tmp = cur; cur = nxt; nxt = tmp;
    }

    head_kernel<<<BATCH * Lcur, 128>>>(cur, wout_w, wout_b, (float*)d_out);
}